// round 16
// baseline (speedup 1.0000x reference)
#include <cuda_runtime.h>
#include <cuda_fp16.h>
#include <math.h>

#define BB 128
#define CC 64
#define HH 134
#define WW 20
#define HWS 2680
#define NK 335
#define EPSV 1e-8f

__device__ __align__(16) __half g_h [(size_t)BB*CC*HWS];  // relu(conv(x)) [b][c][hw]
__device__ __align__(16) __half g_sa[BB*HWS];             // spatial attention (half)
__device__ float g_ca[BB*CC];
__device__ float g_S [BB*8];

// conv3x3 + relu + per-(b,c) sum/max + CBAM channel-attention MLP, fused.
// grid(BB) x 256; warp w owns channels [8w, 8w+8); block owns batch b entirely.
__global__ __launch_bounds__(256) void k_conv(const float* __restrict__ x,
                                              const float* __restrict__ cw,
                                              const float* __restrict__ cb,
                                              const float* __restrict__ w1,
                                              const float* __restrict__ w2) {
    int b = blockIdx.x;
    __shared__ float tile[136 * 22];                // full image + 1-halo
    __shared__ float avg[64], mxv[64], hid[8];
    const float* xb = x + b * HWS;
    for (int i = threadIdx.x; i < 136 * 22; i += 256) {
        int rr = i / 22 - 1, cc = i % 22 - 1;
        tile[i] = (rr >= 0 && rr < HH && cc >= 0 && cc < WW) ? xb[rr * WW + cc] : 0.f;
    }
    __syncthreads();
    int warp = threadIdx.x >> 5, lane = threadIdx.x & 31, c0 = warp * 8;
    float w[8][9], bias[8], sum[8], mx[8];
#pragma unroll
    for (int j = 0; j < 8; j++) {
#pragma unroll
        for (int t = 0; t < 9; t++) w[j][t] = __ldg(&cw[(c0 + j) * 9 + t]);
        bias[j] = __ldg(&cb[c0 + j]);
        sum[j] = 0.f; mx[j] = 0.f;
    }
    for (int p = lane; p < HWS; p += 32) {
        int lr = p / WW, col = p % WW;
        float win[9];
#pragma unroll
        for (int dr = 0; dr < 3; dr++)
#pragma unroll
            for (int dc = 0; dc < 3; dc++) win[dr * 3 + dc] = tile[(lr + dr) * 22 + col + dc];
#pragma unroll
        for (int j = 0; j < 8; j++) {
            float acc = bias[j];
#pragma unroll
            for (int t = 0; t < 9; t++) acc = fmaf(w[j][t], win[t], acc);
            acc = fmaxf(acc, 0.f);
            g_h[((size_t)b * CC + c0 + j) * HWS + p] = __float2half(acc);
            sum[j] += acc; mx[j] = fmaxf(mx[j], acc);
        }
    }
#pragma unroll
    for (int j = 0; j < 8; j++)
#pragma unroll
        for (int o = 16; o > 0; o >>= 1) {
            sum[j] += __shfl_xor_sync(~0u, sum[j], o);
            mx[j] = fmaxf(mx[j], __shfl_xor_sync(~0u, mx[j], o));
        }
    if (lane == 0)
#pragma unroll
        for (int j = 0; j < 8; j++) {
            avg[c0 + j] = sum[j] * (1.f / HWS);
            mxv[c0 + j] = mx[j];
        }
    __syncthreads();
    int t = threadIdx.x;
    if (t < 8) {
        const float* v = (t < 4) ? avg : mxv;
        int i = t & 3;
        float acc = 0.f;
        for (int c = 0; c < 64; c++) acc += v[c] * __ldg(&w1[i * 64 + c]);
        hid[t] = fmaxf(acc, 0.f);
    }
    __syncthreads();
    if (t < 64) {
        float o = 0.f;
#pragma unroll
        for (int i = 0; i < 4; i++) o += (hid[i] + hid[4 + i]) * __ldg(&w2[t * 4 + i]);
        g_ca[b * 64 + t] = 1.f / (1.f + __expf(-o));
    }
}

// per-pixel channel mean/max of h*ca + 7x7 conv + sigmoid -> g_sa (half);
// accumulate S_e (from the quantized sa, for identity consistency).
// grid(BB) x 256
__global__ __launch_bounds__(256) void k_spa(const float* __restrict__ sw) {
    int b = blockIdx.x;
    __shared__ float tile[2 * 140 * 26];
    __shared__ float wts[98];
    __shared__ float cas[64];
    __shared__ float red[256];
    int tid = threadIdx.x;
    if (tid < 98) wts[tid] = sw[tid];
    if (tid < 64) cas[tid] = g_ca[b * 64 + tid];
    for (int i = tid; i < 2 * 140 * 26; i += 256) tile[i] = 0.f;
    __syncthreads();
    const __half2* hb = (const __half2*)(g_h + (size_t)b * CC * HWS);
    for (int idx = tid; idx < HWS / 2; idx += 256) {
        float s0 = 0.f, s1 = 0.f, m0 = 0.f, m1 = 0.f;
#pragma unroll 8
        for (int c = 0; c < 64; c++) {
            float2 f = __half22float2(hb[c * (HWS / 2) + idx]);
            float ca = cas[c];
            float v0 = f.x * ca, v1 = f.y * ca;
            s0 += v0; s1 += v1;
            m0 = fmaxf(m0, v0); m1 = fmaxf(m1, v1);
        }
        int p0 = idx * 2, p1 = p0 + 1;
        int r0 = p0 / WW, cc0 = p0 % WW, r1 = p1 / WW, cc1 = p1 % WW;
        tile[(r0 + 3) * 26 + cc0 + 3] = s0 * (1.f / 64.f);
        tile[(r1 + 3) * 26 + cc1 + 3] = s1 * (1.f / 64.f);
        tile[140 * 26 + (r0 + 3) * 26 + cc0 + 3] = m0;
        tile[140 * 26 + (r1 + 3) * 26 + cc1 + 3] = m1;
    }
    __syncthreads();
    float Sacc = 0.f;
    for (int p = tid; p < HWS; p += 256) {
        int r = p / WW, c = p % WW;
        float acc = 0.f;
#pragma unroll
        for (int ch = 0; ch < 2; ch++)
            for (int dr = 0; dr < 7; dr++)
#pragma unroll
                for (int dc = 0; dc < 7; dc++)
                    acc = fmaf(wts[ch * 49 + dr * 7 + dc],
                               tile[ch * 140 * 26 + (r + dr) * 26 + c + dc], acc);
        float sa = __fdividef(1.f, 1.f + __expf(-acc));
        __half sah = __float2half(sa);
        g_sa[b * HWS + p] = sah;
        Sacc += __half2float(sah) * tile[(r + 3) * 26 + c + 3];   // sp_mean at p
    }
    red[tid] = Sacc;
    __syncthreads();
    if (tid < 8) {
        float s = 0.f;
        for (int i = tid; i < 256; i += 8) s += red[i];   // p%8 == tid%8
        g_S[b * 8 + tid] = s * 64.f;
    }
}

// Routing math for one iteration, replicated per-warp. Returns d[] in-place.
// iter == 0: logits from S only.  iter == 1: also add T0 contribution.
__device__ __forceinline__ void route_d(const float* __restrict__ cW, int b,
                                        const float* T0s, int iter,
                                        int lane, int jg, float* d) {
    float Wc[8], S[8], acc[8];
#pragma unroll
    for (int e = 0; e < 8; e++) {
        Wc[e] = __ldg(&cW[e * 32 + lane]);
        S[e]  = __ldg(&g_S[b * 8 + e]);
    }
    float s = 0.f;
#pragma unroll
    for (int e = 0; e < 8; e++) s = fmaf(0.5f * S[e], Wc[e], s);
    float ss = s * s;
#pragma unroll
    for (int o = 8; o > 0; o >>= 1) ss += __shfl_xor_sync(~0u, ss, o);
    ss += EPSV;
    float v = (sqrtf(ss) / (1.f + ss)) * s;
#pragma unroll
    for (int e = 0; e < 8; e++) {
        float pa = Wc[e] * v;
#pragma unroll
        for (int o = 8; o > 0; o >>= 1) pa += __shfl_xor_sync(~0u, pa, o);
        acc[e] = pa;
    }
    if (iter == 1) {
        float s2 = 0.f;
#pragma unroll
        for (int e = 0; e < 8; e++) {
            float T0 = T0s[e];
            float te = (jg == 0) ? T0 : S[e] - T0;
            s2 = fmaf(te, Wc[e], s2);
        }
        float ss2 = s2 * s2;
#pragma unroll
        for (int o = 8; o > 0; o >>= 1) ss2 += __shfl_xor_sync(~0u, ss2, o);
        ss2 += EPSV;
        float v2 = (sqrtf(ss2) / (1.f + ss2)) * s2;
#pragma unroll
        for (int e = 0; e < 8; e++) {
            float pa = Wc[e] * v2;
#pragma unroll
            for (int o = 8; o > 0; o >>= 1) pa += __shfl_xor_sync(~0u, pa, o);
            acc[e] += pa;
        }
    }
#pragma unroll
    for (int e = 0; e < 8; e++) {
        float diff = acc[e] - __shfl_xor_sync(~0u, acc[e], 16);
        d[e] = jg ? -diff : diff;
    }
}

// One sweep over u: Te_e += sigmoid(u.d)*u_e for this warp's channels.
__device__ __forceinline__ void sweep_T(int b, int warp, int lane,
                                        const float* d, float* Te) {
    const uint4* hb  = (const uint4*)(g_h  + (size_t)b * CC * HWS);
    const uint4* sab = (const uint4*)(g_sa + (size_t)b * HWS);
#pragma unroll
    for (int rep = 0; rep < 2; rep++) {
        int c = warp + rep * 32;
        float ca = __ldg(&g_ca[b * 64 + c]);
        const uint4* hc = hb + (size_t)c * NK;
#pragma unroll
        for (int it = 0; it < 11; it++) {
            int k = it * 32 + lane;
            if (k < NK) {
                uint4 raw  = hc[k];
                uint4 sraw = sab[k];
                const __half2* hp = (const __half2*)&raw;
                const __half2* sp = (const __half2*)&sraw;
                float us[8];
                float dx0 = 0.f, dx1 = 0.f;
#pragma unroll
                for (int q = 0; q < 2; q++) {
                    float2 uf = __half22float2(hp[q]);
                    float2 sf = __half22float2(sp[q]);
                    us[2 * q]     = uf.x * sf.x;
                    us[2 * q + 1] = uf.y * sf.y;
                    dx0 = fmaf(us[2 * q],     d[2 * q],     dx0);
                    dx0 = fmaf(us[2 * q + 1], d[2 * q + 1], dx0);
                }
#pragma unroll
                for (int q = 2; q < 4; q++) {
                    float2 uf = __half22float2(hp[q]);
                    float2 sf = __half22float2(sp[q]);
                    us[2 * q]     = uf.x * sf.x;
                    us[2 * q + 1] = uf.y * sf.y;
                    dx1 = fmaf(us[2 * q],     d[2 * q],     dx1);
                    dx1 = fmaf(us[2 * q + 1], d[2 * q + 1], dx1);
                }
                float dx = (dx0 + dx1) * ca;
                float sg = __fdividef(ca, 1.f + __expf(-dx));
#pragma unroll
                for (int e = 0; e < 8; e++) Te[e] = fmaf(sg, us[e], Te[e]);
            }
        }
    }
}

// Block-wide reduce of per-warp Te into dst[0..7]. Uses Tsm scratch.
__device__ __forceinline__ void reduce_T(float* Tsm, float* dst,
                                         int warp, int lane, float* Te) {
#pragma unroll
    for (int e = 0; e < 8; e++)
#pragma unroll
        for (int o = 16; o > 0; o >>= 1) Te[e] += __shfl_xor_sync(~0u, Te[e], o);
    if (lane == 0)
#pragma unroll
        for (int e = 0; e < 8; e++) Tsm[warp * 8 + e] = Te[e];
    __syncthreads();
    if (warp == 0) {
        float part[8];
#pragma unroll
        for (int e = 0; e < 8; e++) part[e] = Tsm[lane * 8 + e];
#pragma unroll
        for (int e = 0; e < 8; e++)
#pragma unroll
            for (int o = 16; o > 0; o >>= 1) part[e] += __shfl_xor_sync(~0u, part[e], o);
        if (lane < 8) dst[lane] = part[lane];
    }
    __syncthreads();
}

// Both routing passes fused: sweep1 (DRAM) -> T0 via smem -> sweep2 (L2-hot)
// -> lengths.  grid(BB) x 1024; warp w handles channels w and w+32.
__global__ __launch_bounds__(1024) void k_route(const float* __restrict__ cW,
                                                float* __restrict__ out) {
    int b = blockIdx.x;
    __shared__ float Tsm[32 * 8];
    __shared__ float T0s[8], T1s[8];
    int tid = threadIdx.x, warp = tid >> 5, lane = tid & 31;
    int jg = lane >> 4;

    float d[8], Te[8];
    route_d(cW, b, T0s, 0, lane, jg, d);
#pragma unroll
    for (int e = 0; e < 8; e++) Te[e] = 0.f;
    sweep_T(b, warp, lane, d, Te);
    reduce_T(Tsm, T0s, warp, lane, Te);

    route_d(cW, b, T0s, 1, lane, jg, d);
#pragma unroll
    for (int e = 0; e < 8; e++) Te[e] = 0.f;
    sweep_T(b, warp, lane, d, Te);
    reduce_T(Tsm, T1s, warp, lane, Te);

    if (warp == 0) {
        // iter-3 math: lengths from T1
        float s = 0.f;
#pragma unroll
        for (int e = 0; e < 8; e++) {
            float T1 = T1s[e];
            float te = (jg == 0) ? T1 : __ldg(&g_S[b * 8 + e]) - T1;
            s = fmaf(te, __ldg(&cW[e * 32 + lane]), s);
        }
        float ss = s * s;
#pragma unroll
        for (int o = 8; o > 0; o >>= 1) ss += __shfl_xor_sync(~0u, ss, o);
        ss += EPSV;
        float v = (sqrtf(ss) / (1.f + ss)) * s;
        float vs = v * v;
#pragma unroll
        for (int o = 8; o > 0; o >>= 1) vs += __shfl_xor_sync(~0u, vs, o);
        if ((lane & 15) == 0) out[b * 2 + jg] = sqrtf(vs + EPSV);
    }
}

extern "C" void kernel_launch(void* const* d_in, const int* in_sizes, int n_in,
                              void* d_out, int out_size) {
    const float* x   = (const float*)d_in[0];
    const float* cw  = (const float*)d_in[1];
    const float* cb  = (const float*)d_in[2];
    const float* w1  = (const float*)d_in[3];
    const float* w2  = (const float*)d_in[4];
    const float* sw  = (const float*)d_in[5];
    const float* cpW = (const float*)d_in[6];
    float* out = (float*)d_out;

    k_conv<<<BB, 256>>>(x, cw, cb, w1, w2);
    k_spa<<<BB, 256>>>(sw);
    k_route<<<BB, 1024>>>(cpW, out);
}